// round 17
// baseline (speedup 1.0000x reference)
#include <cuda_runtime.h>
#include <cstdint>

#define Bb 32
#define Ss 256
#define Ll 64
#define Dd 100
#define Mm 20
#define NSLOT (Bb * Mm)   // 640
#define NBLK (NSLOT / 2)  // 320 blocks, 2 slots each (same batch)

typedef unsigned long long ULL;

// ---------------- scratch (no allocations allowed) ----------------
__device__ __align__(16) float  g_enc [Bb * Ss * Dd];      // [B,S,D]
__device__ __align__(16) float2 g_esw [Bb * Ss * Dd];      // [B,S,D] (enc, enc@W^T)
__device__ __align__(16) float  g_kg  [Bb * Ss * Mm];      // [B,S,M] enc . keys[m]

// ---------------- helpers ----------------
__device__ __forceinline__ void fma2(ULL& acc, ULL a, ULL b) {
    asm("fma.rn.f32x2 %0, %1, %2, %0;" : "+l"(acc) : "l"(a), "l"(b));
}
__device__ __forceinline__ ULL pack2(float lo, float hi) {
    ULL r;
    asm("mov.b64 %0, {%1, %2};" : "=l"(r) : "f"(lo), "f"(hi));
    return r;
}
__device__ __forceinline__ float sum2(ULL v) {
    float lo, hi;
    asm("mov.b64 {%0, %1}, %2;" : "=f"(lo), "=f"(hi) : "l"(v));
    return lo + hi;
}
__device__ __forceinline__ void unpack2(ULL v, float& lo, float& hi) {
    asm("mov.b64 {%0, %1}, %2;" : "=f"(lo), "=f"(hi) : "l"(v));
}

// ================= K1: encode (R12-exact float4 path) =================
__global__ void k_encode(const float4* __restrict__ batch4,
                         const float4* __restrict__ mult4,
                         float4* __restrict__ enc4) {
    __shared__ float4 sm4[100];
    int row = blockIdx.x;           // b*S + s
    int t = threadIdx.x;

    if (t < 100) {
        int c  = t % 25;
        int lg = t / 25;
        const float4* bp = batch4 + (size_t)row * (Ll * 25);
        float4 acc = make_float4(0.f, 0.f, 0.f, 0.f);
#pragma unroll
        for (int k = 0; k < 16; ++k) {
            int l = lg + 4 * k;
            float4 bv = bp[l * 25 + c];
            float4 mv = __ldg(&mult4[l * 25 + c]);
            acc.x += bv.x * mv.x;
            acc.y += bv.y * mv.y;
            acc.z += bv.z * mv.z;
            acc.w += bv.w * mv.w;
        }
        sm4[t] = acc;
    }
    __syncthreads();
    if (t < 25) {
        float4 a = sm4[t], b = sm4[t + 25], c = sm4[t + 50], d = sm4[t + 75];
        float4 r;
        r.x = (a.x + b.x) + (c.x + d.x);
        r.y = (a.y + b.y) + (c.y + d.y);
        r.z = (a.z + b.z) + (c.z + d.z);
        r.w = (a.w + b.w) + (c.w + d.w);
        enc4[(size_t)row * 25 + t] = r;
    }
}

// ================= K2: project (tiled GEMM, R12-exact) =================
#define PRT 64
#define DCH 25
#define EPITCH 106
__global__ void __launch_bounds__(128, 1)
k_project(const float* __restrict__ W, const float* __restrict__ keys) {
    __shared__ __align__(16) float encs[PRT * EPITCH];   // 27.1 KB
    __shared__ __align__(16) float Z[DCH * 128];         // 12.8 KB
    int t = threadIdx.x;
    int ex = t & 7, ry = t >> 3;          // ex<8, ry<16
    int row0 = blockIdx.x * PRT;

    for (int i = t; i < PRT * Dd; i += 128) {
        int r = i / Dd, c = i % Dd;
        encs[r * EPITCH + c] = g_enc[(size_t)(row0 + r) * Dd + c];
    }

    ULL acc[4][8];
#pragma unroll
    for (int i = 0; i < 4; ++i)
#pragma unroll
        for (int g = 0; g < 8; ++g) acc[i][g] = 0ull;

    for (int d0 = 0; d0 < Dd; d0 += DCH) {
        __syncthreads();
        for (int i = t; i < DCH * 128; i += 128) {
            int dd = i >> 7, n = i & 127;
            int d = d0 + dd;
            float v = 0.f;
            if (n < 100)      v = __ldg(&W[n * Dd + d]);
            else if (n < 120) v = __ldg(&keys[(n - 100) * Dd + d]);
            Z[dd * 128 + n] = v;
        }
        __syncthreads();
#pragma unroll 5
        for (int dd = 0; dd < DCH; ++dd) {
            ULL z2[8];
#pragma unroll
            for (int g = 0; g < 4; ++g) {
                float4 zv = *(const float4*)&Z[dd * 128 + 4 * ex + 32 * g];
                z2[2 * g]     = pack2(zv.x, zv.y);
                z2[2 * g + 1] = pack2(zv.z, zv.w);
            }
#pragma unroll
            for (int i = 0; i < 4; ++i) {
                float rv = encs[(ry * 4 + i) * EPITCH + d0 + dd];
                ULL r2 = pack2(rv, rv);
#pragma unroll
                for (int g = 0; g < 8; ++g) fma2(acc[i][g], r2, z2[g]);
            }
        }
    }
    __syncthreads();

#pragma unroll
    for (int i = 0; i < 4; ++i) {
        int rl = ry * 4 + i;
        int row = row0 + rl;
#pragma unroll
        for (int g = 0; g < 4; ++g) {
            float v0, v1, v2, v3;
            unpack2(acc[i][2 * g], v0, v1);
            unpack2(acc[i][2 * g + 1], v2, v3);
            float vv[4] = {v0, v1, v2, v3};
#pragma unroll
            for (int k = 0; k < 4; ++k) {
                int cj = 4 * ex + 32 * g + k;
                if (cj < 100) {
                    g_esw[(size_t)row * Dd + cj] =
                        make_float2(encs[rl * EPITCH + cj], vv[k]);
                } else if (cj < 120) {
                    g_kg[(size_t)row * Mm + (cj - 100)] = vv[k];
                }
            }
        }
    }
}

// ================= K3: scan (R12-exact core + phase skew) =================
// Co-resident blocks {bid, bid+148, bid+296} get staggered starts
// (~0/700/1400 cyc) so their FMA phases overlap each other's serial tails
// instead of phase-locking.
__global__ void __launch_bounds__(128, 3)
k_scan(const float* __restrict__ keys, const float* __restrict__ U,
       const float* __restrict__ V, const float* __restrict__ prelu_a,
       float* __restrict__ out) {
    __shared__ __align__(16) float h0s[104];     // pads [100,104) = 0
    __shared__ __align__(16) float h1s[104];
    __shared__ float part[2][4][128];            // [slot][dwarp][e]
    __shared__ float4 redA[4];                   // (wp0, wp1, hc0, hc1)
    __shared__ float2 redB[4];                   // (cc0, cc1)

    int bid = blockIdx.x;
    int sl0 = 2 * bid, sl1 = sl0 + 1;
    int b  = sl0 / Mm;
    int m0 = sl0 % Mm, m1 = m0 + 1;              // m0 even -> same batch

    int t = threadIdx.x;
    int lane = t & 31, w = t >> 5;
    bool act = (t < Dd);
    float aprelu = __ldg(prelu_a);

    // ---- U quarter-tile: 4 e-rows x 13 d-pairs (my warp's d-range) ----
    ULL U2[4][13];
#pragma unroll
    for (int j = 0; j < 4; ++j) {
        int e = lane + 32 * j;
#pragma unroll
        for (int k = 0; k < 13; ++k) {
            int d = 26 * w + 2 * k;
            float u0 = (e < Dd && d     < Dd) ? __ldg(&U[e * Dd + d])     : 0.f;
            float u1 = (e < Dd && d + 1 < Dd) ? __ldg(&U[e * Dd + d + 1]) : 0.f;
            U2[j][k] = pack2(u0, u1);
        }
    }

    // ---- step-invariant keysV[m,e] on state mapping ----
    float kv0 = 0.f, kv1 = 0.f;
    if (act) {
#pragma unroll 4
        for (int d = 0; d < Dd; ++d) {
            float ve = __ldg(&V[t * Dd + d]);
            kv0 += __ldg(&keys[m0 * Dd + d]) * ve;
            kv1 += __ldg(&keys[m1 * Dd + d]) * ve;
        }
    }

    // ---- init: h = raw keys; hh = ||keys||^2 ----
    if (t < 104) { h0s[t] = 0.f; h1s[t] = 0.f; }
    __syncthreads();
    float hold0 = act ? __ldg(&keys[m0 * Dd + t]) : 0.f;
    float hold1 = act ? __ldg(&keys[m1 * Dd + t]) : 0.f;
    if (act) { h0s[t] = hold0; h1s[t] = hold1; }
    {
        float q0 = hold0 * hold0, q1 = hold1 * hold1;
#pragma unroll
        for (int o = 16; o > 0; o >>= 1) {
            q0 += __shfl_down_sync(0xffffffffu, q0, o);
            q1 += __shfl_down_sync(0xffffffffu, q1, o);
        }
        if (lane == 0) redB[w] = make_float2(q0, q1);
    }
    __syncthreads();
    float hh0 = redB[0].x + redB[1].x + redB[2].x + redB[3].x;
    float hh1 = redB[0].y + redB[1].y + redB[2].y + redB[3].y;

    const float2* eswp = g_esw + (size_t)b * Ss * Dd;
    const float2* kgp  = (const float2*)(g_kg + (size_t)b * Ss * Mm + m0);

    float2 esw = act ? eswp[t] : make_float2(0.f, 0.f);
    float2 kg  = __ldg(&kgp[0]);
    __syncthreads();

    // ---- phase skew: stagger co-resident blocks by ~1/3 step ----
    {
        int skew = (bid / 148) * 175;            // 0 / 175 / 350 dependent FMAs
        float dv = (float)(bid & 3) + 1.5f;
#pragma unroll 1
        for (int i = 0; i < skew; ++i)
            asm volatile("fma.rn.f32 %0, %0, %1, %2;"
                         : "+f"(dv) : "f"(1.0000001f), "f"(1e-30f));
    }

    const ULL* h0u = (const ULL*)h0s;
    const ULL* h1u = (const ULL*)h1s;

    for (int s = 0; s < Ss; ++s) {
        // ---- matvec partials: my warp's 26-dim d-range, 4 e's, 2 slots ----
        ULL a0[4] = {0, 0, 0, 0};
        ULL a1[4] = {0, 0, 0, 0};
        int hb = 13 * w;
#pragma unroll
        for (int k = 0; k < 13; ++k) {
            ULL x = h0u[hb + k];
            ULL y = h1u[hb + k];
            fma2(a0[0], x, U2[0][k]);
            fma2(a1[0], y, U2[0][k]);
            fma2(a0[1], x, U2[1][k]);
            fma2(a1[1], y, U2[1][k]);
            fma2(a0[2], x, U2[2][k]);
            fma2(a1[2], y, U2[2][k]);
            fma2(a0[3], x, U2[3][k]);
            fma2(a1[3], y, U2[3][k]);
        }
#pragma unroll
        for (int j = 0; j < 4; ++j) {
            int e = lane + 32 * j;
            part[0][w][e] = sum2(a0[j]);
            part[1][w][e] = sum2(a1[j]);
        }
        __syncthreads();   // bar A: partials visible; h reads done

        // ---- gather candidates on state mapping ----
        float p0 = (part[0][0][t] + part[0][1][t]) + (part[0][2][t] + part[0][3][t]);
        float p1 = (part[1][0][t] + part[1][1][t]) + (part[1][2][t] + part[1][3][t]);
        float c0 = kv0 + esw.y + p0;
        float c1 = kv1 + esw.y + p1;
        c0 = (c0 >= 0.f) ? c0 : aprelu * c0;
        c1 = (c1 >= 0.f) ? c1 : aprelu * c1;

        // ---- prefetch next step's inputs ----
        float2 eswn = esw, kgn = kg;
        if (s + 1 < Ss) {
            eswn = act ? eswp[(size_t)(s + 1) * Dd + t] : make_float2(0.f, 0.f);
            kgn  = __ldg(&kgp[(size_t)(s + 1) * (Mm / 2)]);
        }

        // ---- merged reductions: wp (hold.enc), hc (hold.c), cc (c.c) ----
        float wp0 = hold0 * esw.x, wp1 = hold1 * esw.x;
        float hc0 = hold0 * c0,    hc1 = hold1 * c1;
        float cc0 = c0 * c0,       cc1 = c1 * c1;
#pragma unroll
        for (int o = 16; o > 0; o >>= 1) {
            wp0 += __shfl_down_sync(0xffffffffu, wp0, o);
            wp1 += __shfl_down_sync(0xffffffffu, wp1, o);
            hc0 += __shfl_down_sync(0xffffffffu, hc0, o);
            hc1 += __shfl_down_sync(0xffffffffu, hc1, o);
            cc0 += __shfl_down_sync(0xffffffffu, cc0, o);
            cc1 += __shfl_down_sync(0xffffffffu, cc1, o);
        }
        if (lane == 0) {
            redA[w] = make_float4(wp0, wp1, hc0, hc1);
            redB[w] = make_float2(cc0, cc1);
        }
        __syncthreads();   // bar B: reductions visible

        float4 A = redA[0], B4 = redA[1], C4 = redA[2], D4 = redA[3];
        float2 E = redB[0], F = redB[1], G2 = redB[2], H2 = redB[3];
        float mg0 = (A.x + B4.x) + (C4.x + D4.x);
        float mg1 = (A.y + B4.y) + (C4.y + D4.y);
        float shc0 = (A.z + B4.z) + (C4.z + D4.z);
        float shc1 = (A.w + B4.w) + (C4.w + D4.w);
        float scc0 = (E.x + F.x) + (G2.x + H2.x);
        float scc1 = (E.y + F.y) + (G2.y + H2.y);

        float g0 = 1.f / (1.f + __expf(-(mg0 + kg.x)));
        float g1 = 1.f / (1.f + __expf(-(mg1 + kg.y)));
        // ||hn||^2 = hh + 2 g (hold.c) + g^2 (c.c)
        float n0 = hh0 + 2.f * g0 * shc0 + g0 * g0 * scc0;
        float n1 = hh1 + 2.f * g1 * shc1 + g1 * g1 * scc1;
        float r0 = rsqrtf(n0);
        float r1 = rsqrtf(n1);

        float hn0 = (hold0 + c0 * g0) * r0;   // normalized
        float hn1 = (hold1 + c1 * g1) * r1;
        if (!act) { hn0 = 0.f; hn1 = 0.f; }
        if (act) { h0s[t] = hn0; h1s[t] = hn1; }
        __syncthreads();   // bar C: h visible for next matvec

        hold0 = hn0;
        hold1 = hn1;
        hh0 = 1.f;
        hh1 = 1.f;
        esw = eswn;
        kg = kgn;
    }

    if (act) {
        out[(size_t)sl0 * Dd + t] = hold0;
        out[(size_t)sl1 * Dd + t] = hold1;
    }
}

// ================= launcher =================
extern "C" void kernel_launch(void* const* d_in, const int* in_sizes, int n_in,
                              void* d_out, int out_size) {
    const float* batch = (const float*)d_in[0];  // [B,S,L,D]
    const float* mult  = (const float*)d_in[1];  // [L,D]
    const float* keys  = (const float*)d_in[2];  // [M,D]
    const float* U     = (const float*)d_in[3];  // [D,D]
    const float* V     = (const float*)d_in[4];  // [D,D]
    const float* W     = (const float*)d_in[5];  // [D,D]
    const float* pa    = (const float*)d_in[6];  // scalar
    float* out = (float*)d_out;                  // [B,M,D]

    float4* enc4;
    cudaGetSymbolAddress((void**)&enc4, g_enc);

    k_encode<<<Bb * Ss, 128>>>((const float4*)batch, (const float4*)mult, enc4);
    k_project<<<(Bb * Ss) / PRT, 128>>>(W, keys);
    k_scan<<<NBLK, 128>>>(keys, U, V, pa, out);
}